// round 1
// baseline (speedup 1.0000x reference)
#include <cuda_runtime.h>
#include <math.h>

#define FD 16
#define ED 32
#define HD 16
#define MAXB 131072

// Scratch (allocation-free): var_out [B, F*H] and folded embedder matrices.
__device__ float g_var[(size_t)MAXB * FD * HD];
__device__ float g_A1[FD * HD];
__device__ float g_C1[FD * HD];
__device__ float g_As[FD * HD];
__device__ float g_Cs[FD * HD];

// ---------------------------------------------------------------------------
// Fold Linear(1,E) embedder into the GRN first-layer / skip-layer weights:
//   h_pre[f,j]  = x_f * A1[f,j] + C1[f,j]
//   skip[f,j]   = x_f * As[f,j] + Cs[f,j]
// ---------------------------------------------------------------------------
__global__ void precompute_kernel(const float* __restrict__ emb_w,
                                  const float* __restrict__ emb_b,
                                  const float* __restrict__ w1,
                                  const float* __restrict__ b1,
                                  const float* __restrict__ ws,
                                  const float* __restrict__ bs) {
    int t = threadIdx.x;            // 0..255 = f*16 + j
    int f = t >> 4;
    const float* ew = emb_w + f * ED;
    const float* eb = emb_b + f * ED;
    const float* W1 = w1 + (size_t)t * ED;   // grn_w1[f][j][:]
    const float* Ws = ws + (size_t)t * ED;   // grn_ws[f][j][:]
    float a1 = 0.f, c1 = 0.f, as_ = 0.f, cs = 0.f;
#pragma unroll
    for (int e = 0; e < ED; e++) {
        float we = ew[e], be = eb[e];
        a1  = fmaf(we, W1[e], a1);
        c1  = fmaf(be, W1[e], c1);
        as_ = fmaf(we, Ws[e], as_);
        cs  = fmaf(be, Ws[e], cs);
    }
    g_A1[t] = a1;
    g_C1[t] = c1 + b1[t];
    g_As[t] = as_;
    g_Cs[t] = cs + bs[t];
}

// ---------------------------------------------------------------------------
// Kernel A: per-row, per-feature GRN + LayerNorm -> g_var[row][f*16+j]
// One thread per row. Hot weights in static smem (40 KB).
// ---------------------------------------------------------------------------
__global__ __launch_bounds__(256) void var_grn_kernel(
    const float* __restrict__ x_tab,
    const float* __restrict__ w2, const float* __restrict__ b2,
    const float* __restrict__ wg, const float* __restrict__ bg,
    const float* __restrict__ gamma, const float* __restrict__ beta,
    int Bn)
{
    __shared__ float sA1[256], sC1[256], sAs[256], sCs[256];
    __shared__ float sW2[4096], sWg[4096];
    __shared__ float sB2[256], sBg[256], sG[256], sBe[256];
    int tid = threadIdx.x;
    sA1[tid] = g_A1[tid]; sC1[tid] = g_C1[tid];
    sAs[tid] = g_As[tid]; sCs[tid] = g_Cs[tid];
    sB2[tid] = b2[tid];   sBg[tid] = bg[tid];
    sG[tid]  = gamma[tid]; sBe[tid] = beta[tid];
    for (int i = tid; i < 4096; i += 256) { sW2[i] = w2[i]; sWg[i] = wg[i]; }
    __syncthreads();

    int row = blockIdx.x * 256 + tid;
    if (row >= Bn) return;
    const float* xr = x_tab + (size_t)row * FD;
    float* vout = g_var + (size_t)row * (FD * HD);

#pragma unroll 1
    for (int f = 0; f < FD; f++) {
        float xf = __ldg(xr + f);
        int fb = f * 16;
        // h = elu(x_f * A1 + C1)
        float hh[16];
#pragma unroll
        for (int j = 0; j < 16; j++) {
            float t = fmaf(xf, sA1[fb + j], sC1[fb + j]);
            hh[j] = t > 0.f ? t : expm1f(t);
        }
        // o = h @ w2[f].T + b2[f]
        float o[16];
#pragma unroll
        for (int k = 0; k < 16; k++) {
            float acc = sB2[fb + k];
            const float* wr = &sW2[(fb + k) * 16];
#pragma unroll
            for (int h = 0; h < 16; h++) acc = fmaf(hh[h], wr[h], acc);
            o[k] = acc;
        }
        // gate + skip + pre-LN sum
        float v[16];
        float mu = 0.f;
#pragma unroll
        for (int j = 0; j < 16; j++) {
            float acc = sBg[fb + j];
            const float* wr = &sWg[(fb + j) * 16];
#pragma unroll
            for (int k = 0; k < 16; k++) acc = fmaf(o[k], wr[k], acc);
            float sg = 1.f / (1.f + expf(-acc));
            float skip = fmaf(xf, sAs[fb + j], sCs[fb + j]);
            float vv = o[j] * sg + skip;
            v[j] = vv;
            mu += vv;
        }
        mu *= (1.f / 16.f);
        float varv = 0.f;
#pragma unroll
        for (int j = 0; j < 16; j++) { float d = v[j] - mu; varv = fmaf(d, d, varv); }
        varv *= (1.f / 16.f);
        float rs = rsqrtf(varv + 1e-5f);
#pragma unroll
        for (int q = 0; q < 4; q++) {
            float4 st;
            st.x = (v[q*4+0] - mu) * rs * sG[fb+q*4+0] + sBe[fb+q*4+0];
            st.y = (v[q*4+1] - mu) * rs * sG[fb+q*4+1] + sBe[fb+q*4+1];
            st.z = (v[q*4+2] - mu) * rs * sG[fb+q*4+2] + sBe[fb+q*4+2];
            st.w = (v[q*4+3] - mu) * rs * sG[fb+q*4+3] + sBe[fb+q*4+3];
            *(float4*)(vout + fb + q * 4) = st;
        }
    }
}

// ---------------------------------------------------------------------------
// Kernel B: weight-GRN + softmax (weights out) + selection + MLP + regressor.
// One thread per row. All head weights in dynamic smem (~56.6 KB).
// ---------------------------------------------------------------------------
#define OFF_W1   0
#define OFF_WS   4096
#define OFF_W2   8192
#define OFF_WGG  8448
#define OFF_B1   8704
#define OFF_B2F  8720
#define OFF_BGG  8736
#define OFF_BS   8752
#define OFF_G    8768
#define OFF_BE   8784
#define OFF_MW1  8800
#define OFF_MB1  9824
#define OFF_MW2  9888
#define OFF_MB2  11936
#define OFF_RW1  11968
#define OFF_RB1  14016
#define OFF_RW2  14080
#define OFF_RB2  14144
#define SMEMB_FLOATS 14145

__global__ __launch_bounds__(256) void sel_mlp_kernel(
    const float* __restrict__ wg_w1, const float* __restrict__ wg_b1,
    const float* __restrict__ wg_w2, const float* __restrict__ wg_b2,
    const float* __restrict__ wg_wgm, const float* __restrict__ wg_bg,
    const float* __restrict__ wg_ws, const float* __restrict__ wg_bs,
    const float* __restrict__ wg_g, const float* __restrict__ wg_beta,
    const float* __restrict__ mlp_w1, const float* __restrict__ mlp_b1,
    const float* __restrict__ mlp_w2, const float* __restrict__ mlp_b2,
    const float* __restrict__ reg_w1, const float* __restrict__ reg_b1,
    const float* __restrict__ reg_w2, const float* __restrict__ reg_b2,
    float* __restrict__ out, float* __restrict__ wout, int Bn)
{
    extern __shared__ float s[];
    int tid = threadIdx.x;
    for (int i = tid; i < 4096; i += 256) { s[OFF_W1+i] = wg_w1[i]; s[OFF_WS+i] = wg_ws[i]; }
    if (tid < 256) { s[OFF_W2+tid] = wg_w2[tid]; s[OFF_WGG+tid] = wg_wgm[tid]; }
    for (int i = tid; i < 2048; i += 256) { s[OFF_MW2+i] = mlp_w2[i]; s[OFF_RW1+i] = reg_w1[i]; }
    for (int i = tid; i < 1024; i += 256) s[OFF_MW1+i] = mlp_w1[i];
    if (tid < 64) { s[OFF_MB1+tid] = mlp_b1[tid]; s[OFF_RB1+tid] = reg_b1[tid]; s[OFF_RW2+tid] = reg_w2[tid]; }
    if (tid < 32) s[OFF_MB2+tid] = mlp_b2[tid];
    if (tid < 16) {
        s[OFF_B1+tid]  = wg_b1[tid];  s[OFF_B2F+tid] = wg_b2[tid];
        s[OFF_BGG+tid] = wg_bg[tid];  s[OFF_BS+tid]  = wg_bs[tid];
        s[OFF_G+tid]   = wg_g[tid];   s[OFF_BE+tid]  = wg_beta[tid];
    }
    if (tid == 0) s[OFF_RB2] = reg_b2[0];
    __syncthreads();

    int row = blockIdx.x * 256 + tid;
    if (row >= Bn) return;
    const float* vr = g_var + (size_t)row * 256;

    // Weight GRN: stream flat feature-by-feature, accumulate hw & skw.
    float hw[16], skw[16];
#pragma unroll
    for (int j = 0; j < 16; j++) { hw[j] = 0.f; skw[j] = 0.f; }
#pragma unroll 1
    for (int f = 0; f < 16; f++) {
        float v[16];
#pragma unroll
        for (int q = 0; q < 4; q++) {
            float4 t = *(const float4*)(vr + f * 16 + q * 4);
            v[q*4] = t.x; v[q*4+1] = t.y; v[q*4+2] = t.z; v[q*4+3] = t.w;
        }
#pragma unroll
        for (int j = 0; j < 16; j++) {
            const float* wa = &s[OFF_W1 + j * 256 + f * 16];
            const float* wb = &s[OFF_WS + j * 256 + f * 16];
            float a = hw[j], b = skw[j];
#pragma unroll
            for (int h = 0; h < 16; h++) { a = fmaf(v[h], wa[h], a); b = fmaf(v[h], wb[h], b); }
            hw[j] = a; skw[j] = b;
        }
    }
#pragma unroll
    for (int j = 0; j < 16; j++) {
        float t = hw[j] + s[OFF_B1 + j];
        hw[j] = t > 0.f ? t : expm1f(t);
        skw[j] += s[OFF_BS + j];
    }
    // ow = hw @ wg_w2.T + b2 ; gate ; + skw ; LN ; softmax
    float ow[16];
#pragma unroll
    for (int j = 0; j < 16; j++) {
        float acc = s[OFF_B2F + j];
        const float* wr = &s[OFF_W2 + j * 16];
#pragma unroll
        for (int h = 0; h < 16; h++) acc = fmaf(hw[h], wr[h], acc);
        ow[j] = acc;
    }
    float gv[16];
#pragma unroll
    for (int i = 0; i < 16; i++) {
        float acc = s[OFF_BGG + i];
        const float* wr = &s[OFF_WGG + i * 16];
#pragma unroll
        for (int ff = 0; ff < 16; ff++) acc = fmaf(ow[ff], wr[ff], acc);
        gv[i] = acc;
    }
    float l[16];
    float mu = 0.f;
#pragma unroll
    for (int i = 0; i < 16; i++) {
        float sg = 1.f / (1.f + expf(-gv[i]));
        float li = ow[i] * sg + skw[i];
        l[i] = li; mu += li;
    }
    mu *= (1.f / 16.f);
    float varv = 0.f;
#pragma unroll
    for (int i = 0; i < 16; i++) { float d = l[i] - mu; varv = fmaf(d, d, varv); }
    varv *= (1.f / 16.f);
    float rs = rsqrtf(varv + 1e-5f);
    float wt[16];
    float mx = -1e30f;
#pragma unroll
    for (int i = 0; i < 16; i++) {
        float li = (l[i] - mu) * rs * s[OFF_G + i] + s[OFF_BE + i];
        wt[i] = li;
        mx = fmaxf(mx, li);
    }
    float sum = 0.f;
#pragma unroll
    for (int i = 0; i < 16; i++) { wt[i] = expf(wt[i] - mx); sum += wt[i]; }
    float inv = 1.f / sum;
#pragma unroll
    for (int i = 0; i < 16; i++) wt[i] *= inv;

    if (wout) {
        float* wo = wout + (size_t)row * 16;
#pragma unroll
        for (int q = 0; q < 4; q++) {
            float4 st; st.x = wt[q*4]; st.y = wt[q*4+1]; st.z = wt[q*4+2]; st.w = wt[q*4+3];
            *(float4*)(wo + q * 4) = st;
        }
    }

    // sel[h] = sum_f var_out[f,h] * wt[f]   (second streamed pass, L2-resident)
    float sel[16];
#pragma unroll
    for (int h = 0; h < 16; h++) sel[h] = 0.f;
#pragma unroll
    for (int f = 0; f < 16; f++) {
        float wf = wt[f];
#pragma unroll
        for (int q = 0; q < 4; q++) {
            float4 t = *(const float4*)(vr + f * 16 + q * 4);
            sel[q*4]   = fmaf(t.x, wf, sel[q*4]);
            sel[q*4+1] = fmaf(t.y, wf, sel[q*4+1]);
            sel[q*4+2] = fmaf(t.z, wf, sel[q*4+2]);
            sel[q*4+3] = fmaf(t.w, wf, sel[q*4+3]);
        }
    }

    // MLP 16->64->32, regressor 32->64->1 (last layer fused into the dot)
    float m1[64];
#pragma unroll
    for (int i = 0; i < 64; i++) {
        float a = s[OFF_MB1 + i];
        const float* wr = &s[OFF_MW1 + i * 16];
#pragma unroll
        for (int h = 0; h < 16; h++) a = fmaf(sel[h], wr[h], a);
        m1[i] = fmaxf(a, 0.f);
    }
    float m2[32];
#pragma unroll
    for (int i = 0; i < 32; i++) {
        float a = s[OFF_MB2 + i];
        const float* wr = &s[OFF_MW2 + i * 64];
#pragma unroll
        for (int j = 0; j < 64; j++) a = fmaf(m1[j], wr[j], a);
        m2[i] = fmaxf(a, 0.f);
    }
    float acc_out = s[OFF_RB2];
#pragma unroll
    for (int i = 0; i < 64; i++) {
        float a = s[OFF_RB1 + i];
        const float* wr = &s[OFF_RW1 + i * 32];
#pragma unroll
        for (int j = 0; j < 32; j++) a = fmaf(m2[j], wr[j], a);
        acc_out = fmaf(fmaxf(a, 0.f), s[OFF_RW2 + i], acc_out);
    }
    out[row] = acc_out;
}

// ---------------------------------------------------------------------------
extern "C" void kernel_launch(void* const* d_in, const int* in_sizes, int n_in,
                              void* d_out, int out_size) {
    const float* x_tab    = (const float*)d_in[0];
    const float* emb_w    = (const float*)d_in[1];
    const float* emb_b    = (const float*)d_in[2];
    const float* grn_w1   = (const float*)d_in[3];
    const float* grn_b1   = (const float*)d_in[4];
    const float* grn_w2   = (const float*)d_in[5];
    const float* grn_b2   = (const float*)d_in[6];
    const float* grn_wg   = (const float*)d_in[7];
    const float* grn_bg   = (const float*)d_in[8];
    const float* grn_ws   = (const float*)d_in[9];
    const float* grn_bs   = (const float*)d_in[10];
    const float* grn_g    = (const float*)d_in[11];
    const float* grn_beta = (const float*)d_in[12];
    const float* wg_w1    = (const float*)d_in[13];
    const float* wg_b1    = (const float*)d_in[14];
    const float* wg_w2    = (const float*)d_in[15];
    const float* wg_b2    = (const float*)d_in[16];
    const float* wg_wgm   = (const float*)d_in[17];
    const float* wg_bg    = (const float*)d_in[18];
    const float* wg_ws    = (const float*)d_in[19];
    const float* wg_bs    = (const float*)d_in[20];
    const float* wg_g     = (const float*)d_in[21];
    const float* wg_beta  = (const float*)d_in[22];
    const float* mlp_w1   = (const float*)d_in[23];
    const float* mlp_b1   = (const float*)d_in[24];
    const float* mlp_w2   = (const float*)d_in[25];
    const float* mlp_b2   = (const float*)d_in[26];
    const float* reg_w1   = (const float*)d_in[27];
    const float* reg_b1   = (const float*)d_in[28];
    const float* reg_w2   = (const float*)d_in[29];
    const float* reg_b2   = (const float*)d_in[30];

    int Bn = in_sizes[0] / FD;
    float* out = (float*)d_out;
    float* wout = (out_size >= Bn * (FD + 1)) ? (out + Bn) : nullptr;

    cudaFuncSetAttribute(sel_mlp_kernel,
                         cudaFuncAttributeMaxDynamicSharedMemorySize,
                         SMEMB_FLOATS * (int)sizeof(float));

    precompute_kernel<<<1, 256>>>(emb_w, emb_b, grn_w1, grn_b1, grn_ws, grn_bs);
    int grid = (Bn + 255) / 256;
    var_grn_kernel<<<grid, 256>>>(x_tab, grn_w2, grn_b2, grn_wg, grn_bg,
                                  grn_g, grn_beta, Bn);
    sel_mlp_kernel<<<grid, 256, SMEMB_FLOATS * sizeof(float)>>>(
        wg_w1, wg_b1, wg_w2, wg_b2, wg_wgm, wg_bg, wg_ws, wg_bs, wg_g, wg_beta,
        mlp_w1, mlp_b1, mlp_w2, mlp_b2, reg_w1, reg_b1, reg_w2, reg_b2,
        out, wout, Bn);
}

// round 3
// speedup vs baseline: 1.1882x; 1.1882x over previous
#include <cuda_runtime.h>
#include <math.h>

#define FD 16
#define HD 16
#define ED 32
#define MAXB 131072

// Transposed scratch: g_var4[chunk][row], chunk = f*4+q (64 chunks of float4).
// Coalesced stores in kernel A, coalesced loads in kernel B.
__device__ float4 g_var4[(size_t)64 * MAXB];

__device__ __forceinline__ float fast_elu(float t) {
    // t>0 -> t ; t<=0 -> exp(t)-1   (branchless)
    return fmaxf(t, 0.f) + (__expf(fminf(t, 0.f)) - 1.f);
}
__device__ __forceinline__ float fast_sig(float x) {
    float t;
    asm("tanh.approx.f32 %0, %1;" : "=f"(t) : "f"(0.5f * x));
    return fmaf(0.5f, t, 0.5f);
}

// ---------------------------------------------------------------------------
// Kernel A: embedder-folded per-feature GRN + LayerNorm.
// 256 threads/block, 2 rows/thread. Embedder fold recomputed per block.
// ---------------------------------------------------------------------------
__global__ __launch_bounds__(256) void var_grn_kernel(
    const float* __restrict__ x_tab,
    const float* __restrict__ emb_w, const float* __restrict__ emb_b,
    const float* __restrict__ w1g, const float* __restrict__ b1g,
    const float* __restrict__ wsg, const float* __restrict__ bsg,
    const float* __restrict__ w2, const float* __restrict__ b2,
    const float* __restrict__ wg, const float* __restrict__ bg,
    const float* __restrict__ gamma, const float* __restrict__ beta,
    int Bn)
{
    __shared__ float sA1[256], sC1[256], sAs[256], sCs[256];
    __shared__ float sW2[4096], sWg[4096];
    __shared__ float sB2[256], sBg[256], sG[256], sBe[256];
    int tid = threadIdx.x;
    {
        // Fold Linear(1,E) embedder into GRN input/skip: per-element dot over E=32.
        int f = tid >> 4;
        const float* ew = emb_w + f * 32;
        const float* eb = emb_b + f * 32;
        const float* W1 = w1g + (size_t)tid * 32;
        const float* Ws = wsg + (size_t)tid * 32;
        float a1 = 0.f, c1 = 0.f, as_ = 0.f, cs = 0.f;
#pragma unroll
        for (int e = 0; e < 32; e++) {
            float we = ew[e], be = eb[e];
            a1  = fmaf(we, W1[e], a1);
            c1  = fmaf(be, W1[e], c1);
            as_ = fmaf(we, Ws[e], as_);
            cs  = fmaf(be, Ws[e], cs);
        }
        sA1[tid] = a1;
        sC1[tid] = c1 + b1g[tid];
        sAs[tid] = as_;
        sCs[tid] = cs + bsg[tid];
        sB2[tid] = b2[tid];  sBg[tid] = bg[tid];
        sG[tid]  = gamma[tid]; sBe[tid] = beta[tid];
        for (int i = tid; i < 4096; i += 256) { sW2[i] = w2[i]; sWg[i] = wg[i]; }
    }
    __syncthreads();

    int gid = blockIdx.x * 256 + tid;
    int r0 = gid * 2;
    if (r0 >= Bn) return;
    const float* x0 = x_tab + (size_t)r0 * 16;
    const float* x1 = x_tab + (size_t)r0 * 16 + 16;

#pragma unroll 1
    for (int f = 0; f < 16; f++) {
        int fb = f * 16;
        float xfa = __ldg(x0 + f);
        float xfb = __ldg(x1 + f);

        // h = elu(x_f * A1 + C1), both rows
        float ha[16], hb[16];
#pragma unroll
        for (int j = 0; j < 16; j++) {
            float a1 = sA1[fb + j], c1 = sC1[fb + j];
            ha[j] = fast_elu(fmaf(xfa, a1, c1));
            hb[j] = fast_elu(fmaf(xfb, a1, c1));
        }
        // o = h @ w2[f].T + b2[f]
        float oa[16], ob[16];
#pragma unroll
        for (int k = 0; k < 16; k++) {
            const float4* wr = (const float4*)&sW2[(fb + k) * 16];
            float A = sB2[fb + k], Bv = A;
#pragma unroll
            for (int q = 0; q < 4; q++) {
                float4 w = wr[q];
                A  = fmaf(ha[q*4+0], w.x, A);  A  = fmaf(ha[q*4+1], w.y, A);
                A  = fmaf(ha[q*4+2], w.z, A);  A  = fmaf(ha[q*4+3], w.w, A);
                Bv = fmaf(hb[q*4+0], w.x, Bv); Bv = fmaf(hb[q*4+1], w.y, Bv);
                Bv = fmaf(hb[q*4+2], w.z, Bv); Bv = fmaf(hb[q*4+3], w.w, Bv);
            }
            oa[k] = A; ob[k] = Bv;
        }
        // gate + skip, accumulate LN mean
        float va[16], vb[16];
        float mua = 0.f, mub = 0.f;
#pragma unroll
        for (int j = 0; j < 16; j++) {
            const float4* wr = (const float4*)&sWg[(fb + j) * 16];
            float A = sBg[fb + j], Bv = A;
#pragma unroll
            for (int q = 0; q < 4; q++) {
                float4 w = wr[q];
                A  = fmaf(oa[q*4+0], w.x, A);  A  = fmaf(oa[q*4+1], w.y, A);
                A  = fmaf(oa[q*4+2], w.z, A);  A  = fmaf(oa[q*4+3], w.w, A);
                Bv = fmaf(ob[q*4+0], w.x, Bv); Bv = fmaf(ob[q*4+1], w.y, Bv);
                Bv = fmaf(ob[q*4+2], w.z, Bv); Bv = fmaf(ob[q*4+3], w.w, Bv);
            }
            float as_ = sAs[fb + j], cs = sCs[fb + j];
            float sa = fmaf(xfa, as_, cs);
            float sb = fmaf(xfb, as_, cs);
            float va_ = fmaf(oa[j], fast_sig(A),  sa);
            float vb_ = fmaf(ob[j], fast_sig(Bv), sb);
            va[j] = va_; vb[j] = vb_;
            mua += va_;  mub += vb_;
        }
        mua *= 0.0625f; mub *= 0.0625f;
        float vara = 0.f, varb = 0.f;
#pragma unroll
        for (int j = 0; j < 16; j++) {
            float da = va[j] - mua; vara = fmaf(da, da, vara);
            float db = vb[j] - mub; varb = fmaf(db, db, varb);
        }
        float rsa = rsqrtf(fmaf(vara, 0.0625f, 1e-5f));
        float rsb = rsqrtf(fmaf(varb, 0.0625f, 1e-5f));
#pragma unroll
        for (int q = 0; q < 4; q++) {
            float4 sa, sb;
            float g0 = sG[fb+q*4+0], g1 = sG[fb+q*4+1], g2 = sG[fb+q*4+2], g3 = sG[fb+q*4+3];
            float e0 = sBe[fb+q*4+0], e1 = sBe[fb+q*4+1], e2 = sBe[fb+q*4+2], e3 = sBe[fb+q*4+3];
            sa.x = (va[q*4+0]-mua)*rsa*g0 + e0; sa.y = (va[q*4+1]-mua)*rsa*g1 + e1;
            sa.z = (va[q*4+2]-mua)*rsa*g2 + e2; sa.w = (va[q*4+3]-mua)*rsa*g3 + e3;
            sb.x = (vb[q*4+0]-mub)*rsb*g0 + e0; sb.y = (vb[q*4+1]-mub)*rsb*g1 + e1;
            sb.z = (vb[q*4+2]-mub)*rsb*g2 + e2; sb.w = (vb[q*4+3]-mub)*rsb*g3 + e3;
            size_t base = (size_t)(f * 4 + q) * Bn + r0;
            g_var4[base]     = sa;
            g_var4[base + 1] = sb;
        }
    }
}

// ---------------------------------------------------------------------------
// Kernel B: weight GRN + softmax + selection + MLP + regressor.
// 128 threads/block, 2 rows/thread.
// ---------------------------------------------------------------------------
#define OFF_W1   0
#define OFF_WS   4096
#define OFF_W2   8192
#define OFF_WGG  8448
#define OFF_MW1  8704
#define OFF_MW2  9728
#define OFF_RW1  11776
#define OFF_B1   13824
#define OFF_B2F  13840
#define OFF_BGG  13856
#define OFF_BS   13872
#define OFF_G    13888
#define OFF_BE   13904
#define OFF_MB1  13920
#define OFF_MB2  13984
#define OFF_RB1  14016
#define OFF_RW2  14080
#define OFF_RB2  14144
#define SMEMB_FLOATS 14148

__device__ __forceinline__ void head_mlp_row(
    const float* __restrict__ s, float* hw, float* skw,
    int row, float* __restrict__ out, float* __restrict__ wout, int Bn)
{
#pragma unroll
    for (int j = 0; j < 16; j++) {
        hw[j]  = fast_elu(hw[j] + s[OFF_B1 + j]);
        skw[j] += s[OFF_BS + j];
    }
    // ow = hw @ wg_w2.T + b2
    float ow[16];
#pragma unroll
    for (int j = 0; j < 16; j++) {
        const float4* wr = (const float4*)&s[OFF_W2 + j * 16];
        float a = s[OFF_B2F + j];
#pragma unroll
        for (int q = 0; q < 4; q++) {
            float4 w = wr[q];
            a = fmaf(hw[q*4+0], w.x, a); a = fmaf(hw[q*4+1], w.y, a);
            a = fmaf(hw[q*4+2], w.z, a); a = fmaf(hw[q*4+3], w.w, a);
        }
        ow[j] = a;
    }
    // gate + skip + LN
    float l[16];
    float mu = 0.f;
#pragma unroll
    for (int i = 0; i < 16; i++) {
        const float4* wr = (const float4*)&s[OFF_WGG + i * 16];
        float g = s[OFF_BGG + i];
#pragma unroll
        for (int q = 0; q < 4; q++) {
            float4 w = wr[q];
            g = fmaf(ow[q*4+0], w.x, g); g = fmaf(ow[q*4+1], w.y, g);
            g = fmaf(ow[q*4+2], w.z, g); g = fmaf(ow[q*4+3], w.w, g);
        }
        float li = fmaf(ow[i], fast_sig(g), skw[i]);
        l[i] = li; mu += li;
    }
    mu *= 0.0625f;
    float varv = 0.f;
#pragma unroll
    for (int i = 0; i < 16; i++) { float d = l[i] - mu; varv = fmaf(d, d, varv); }
    float rs = rsqrtf(fmaf(varv, 0.0625f, 1e-5f));
    float wt[16];
    float mx = -1e30f;
#pragma unroll
    for (int i = 0; i < 16; i++) {
        float li = (l[i] - mu) * rs * s[OFF_G + i] + s[OFF_BE + i];
        wt[i] = li;
        mx = fmaxf(mx, li);
    }
    float sum = 0.f;
#pragma unroll
    for (int i = 0; i < 16; i++) { wt[i] = __expf(wt[i] - mx); sum += wt[i]; }
    float inv = 1.f / sum;
#pragma unroll
    for (int i = 0; i < 16; i++) wt[i] *= inv;

    if (wout) {
        float* wo = wout + (size_t)row * 16;
#pragma unroll
        for (int q = 0; q < 4; q++) {
            float4 st; st.x = wt[q*4]; st.y = wt[q*4+1]; st.z = wt[q*4+2]; st.w = wt[q*4+3];
            *(float4*)(wo + q * 4) = st;
        }
    }

    // sel[h] = sum_f v[f,h] * wt[f]  (re-read, L1/L2-hot, coalesced layout)
    float sel[16];
#pragma unroll
    for (int h = 0; h < 16; h++) sel[h] = 0.f;
#pragma unroll 1
    for (int f = 0; f < 16; f++) {
        float wf = wt[f];
#pragma unroll
        for (int q = 0; q < 4; q++) {
            float4 t = g_var4[(size_t)(f * 4 + q) * Bn + row];
            sel[q*4+0] = fmaf(t.x, wf, sel[q*4+0]);
            sel[q*4+1] = fmaf(t.y, wf, sel[q*4+1]);
            sel[q*4+2] = fmaf(t.z, wf, sel[q*4+2]);
            sel[q*4+3] = fmaf(t.w, wf, sel[q*4+3]);
        }
    }

    // MLP 16->64->32 relu, regressor 32->64->1 relu (last layer fused)
    float m1[64];
#pragma unroll 8
    for (int i = 0; i < 64; i++) {
        const float4* wr = (const float4*)&s[OFF_MW1 + i * 16];
        float a = s[OFF_MB1 + i];
#pragma unroll
        for (int q = 0; q < 4; q++) {
            float4 w = wr[q];
            a = fmaf(sel[q*4+0], w.x, a); a = fmaf(sel[q*4+1], w.y, a);
            a = fmaf(sel[q*4+2], w.z, a); a = fmaf(sel[q*4+3], w.w, a);
        }
        m1[i] = fmaxf(a, 0.f);
    }
    float m2[32];
#pragma unroll 4
    for (int i = 0; i < 32; i++) {
        const float4* wr = (const float4*)&s[OFF_MW2 + i * 64];
        float a = s[OFF_MB2 + i];
#pragma unroll
        for (int q = 0; q < 16; q++) {
            float4 w = wr[q];
            a = fmaf(m1[q*4+0], w.x, a); a = fmaf(m1[q*4+1], w.y, a);
            a = fmaf(m1[q*4+2], w.z, a); a = fmaf(m1[q*4+3], w.w, a);
        }
        m2[i] = fmaxf(a, 0.f);
    }
    float acc_out = s[OFF_RB2];
#pragma unroll 8
    for (int i = 0; i < 64; i++) {
        const float4* wr = (const float4*)&s[OFF_RW1 + i * 32];
        float a = s[OFF_RB1 + i];
#pragma unroll
        for (int q = 0; q < 8; q++) {
            float4 w = wr[q];
            a = fmaf(m2[q*4+0], w.x, a); a = fmaf(m2[q*4+1], w.y, a);
            a = fmaf(m2[q*4+2], w.z, a); a = fmaf(m2[q*4+3], w.w, a);
        }
        acc_out = fmaf(fmaxf(a, 0.f), s[OFF_RW2 + i], acc_out);
    }
    out[row] = acc_out;
}

__global__ __launch_bounds__(128) void sel_mlp_kernel(
    const float* __restrict__ wg_w1, const float* __restrict__ wg_b1,
    const float* __restrict__ wg_w2, const float* __restrict__ wg_b2,
    const float* __restrict__ wg_wgm, const float* __restrict__ wg_bg,
    const float* __restrict__ wg_ws, const float* __restrict__ wg_bs,
    const float* __restrict__ wg_g, const float* __restrict__ wg_beta,
    const float* __restrict__ mlp_w1, const float* __restrict__ mlp_b1,
    const float* __restrict__ mlp_w2, const float* __restrict__ mlp_b2,
    const float* __restrict__ reg_w1, const float* __restrict__ reg_b1,
    const float* __restrict__ reg_w2, const float* __restrict__ reg_b2,
    float* __restrict__ out, float* __restrict__ wout, int Bn)
{
    extern __shared__ float s[];
    int tid = threadIdx.x;
    for (int i = tid; i < 4096; i += 128) { s[OFF_W1+i] = wg_w1[i]; s[OFF_WS+i] = wg_ws[i]; }
    for (int i = tid; i < 2048; i += 128) { s[OFF_MW2+i] = mlp_w2[i]; s[OFF_RW1+i] = reg_w1[i]; }
    for (int i = tid; i < 1024; i += 128) s[OFF_MW1+i] = mlp_w1[i];
    for (int i = tid; i < 256; i += 128) { s[OFF_W2+i] = wg_w2[i]; s[OFF_WGG+i] = wg_wgm[i]; }
    if (tid < 64) { s[OFF_MB1+tid] = mlp_b1[tid]; s[OFF_RB1+tid] = reg_b1[tid]; s[OFF_RW2+tid] = reg_w2[tid]; }
    if (tid < 32) s[OFF_MB2+tid] = mlp_b2[tid];
    if (tid < 16) {
        s[OFF_B1+tid]  = wg_b1[tid];  s[OFF_B2F+tid] = wg_b2[tid];
        s[OFF_BGG+tid] = wg_bg[tid];  s[OFF_BS+tid]  = wg_bs[tid];
        s[OFF_G+tid]   = wg_g[tid];   s[OFF_BE+tid]  = wg_beta[tid];
    }
    if (tid == 0) s[OFF_RB2] = reg_b2[0];
    __syncthreads();

    int gid = blockIdx.x * 128 + tid;
    int r0 = gid * 2;
    if (r0 >= Bn) return;

    // Stream flat feature-by-feature, accumulate hw & skw for both rows.
    float hwa[16], hwb[16], ska[16], skb[16];
#pragma unroll
    for (int j = 0; j < 16; j++) { hwa[j]=0.f; hwb[j]=0.f; ska[j]=0.f; skb[j]=0.f; }

#pragma unroll 1
    for (int f = 0; f < 16; f++) {
        float va[16], vb[16];
#pragma unroll
        for (int q = 0; q < 4; q++) {
            size_t base = (size_t)(f * 4 + q) * Bn + r0;
            float4 t = g_var4[base];
            float4 u = g_var4[base + 1];
            va[q*4]=t.x; va[q*4+1]=t.y; va[q*4+2]=t.z; va[q*4+3]=t.w;
            vb[q*4]=u.x; vb[q*4+1]=u.y; vb[q*4+2]=u.z; vb[q*4+3]=u.w;
        }
#pragma unroll
        for (int j = 0; j < 16; j++) {
            const float4* wa = (const float4*)&s[OFF_W1 + j * 256 + f * 16];
            const float4* wb = (const float4*)&s[OFF_WS + j * 256 + f * 16];
            float Aa = hwa[j], Ab = hwb[j], Sa = ska[j], Sb = skb[j];
#pragma unroll
            for (int q = 0; q < 4; q++) {
                float4 w = wa[q];
                Aa = fmaf(va[q*4+0], w.x, Aa); Aa = fmaf(va[q*4+1], w.y, Aa);
                Aa = fmaf(va[q*4+2], w.z, Aa); Aa = fmaf(va[q*4+3], w.w, Aa);
                Ab = fmaf(vb[q*4+0], w.x, Ab); Ab = fmaf(vb[q*4+1], w.y, Ab);
                Ab = fmaf(vb[q*4+2], w.z, Ab); Ab = fmaf(vb[q*4+3], w.w, Ab);
                float4 v2 = wb[q];
                Sa = fmaf(va[q*4+0], v2.x, Sa); Sa = fmaf(va[q*4+1], v2.y, Sa);
                Sa = fmaf(va[q*4+2], v2.z, Sa); Sa = fmaf(va[q*4+3], v2.w, Sa);
                Sb = fmaf(vb[q*4+0], v2.x, Sb); Sb = fmaf(vb[q*4+1], v2.y, Sb);
                Sb = fmaf(vb[q*4+2], v2.z, Sb); Sb = fmaf(vb[q*4+3], v2.w, Sb);
            }
            hwa[j] = Aa; hwb[j] = Ab; ska[j] = Sa; skb[j] = Sb;
        }
    }
    head_mlp_row(s, hwa, ska, r0,     out, wout, Bn);
    head_mlp_row(s, hwb, skb, r0 + 1, out, wout, Bn);
}

// ---------------------------------------------------------------------------
extern "C" void kernel_launch(void* const* d_in, const int* in_sizes, int n_in,
                              void* d_out, int out_size) {
    const float* x_tab    = (const float*)d_in[0];
    const float* emb_w    = (const float*)d_in[1];
    const float* emb_b    = (const float*)d_in[2];
    const float* grn_w1   = (const float*)d_in[3];
    const float* grn_b1   = (const float*)d_in[4];
    const float* grn_w2   = (const float*)d_in[5];
    const float* grn_b2   = (const float*)d_in[6];
    const float* grn_wg   = (const float*)d_in[7];
    const float* grn_bg   = (const float*)d_in[8];
    const float* grn_ws   = (const float*)d_in[9];
    const float* grn_bs   = (const float*)d_in[10];
    const float* grn_g    = (const float*)d_in[11];
    const float* grn_beta = (const float*)d_in[12];
    const float* wg_w1    = (const float*)d_in[13];
    const float* wg_b1    = (const float*)d_in[14];
    const float* wg_w2    = (const float*)d_in[15];
    const float* wg_b2    = (const float*)d_in[16];
    const float* wg_wgm   = (const float*)d_in[17];
    const float* wg_bg    = (const float*)d_in[18];
    const float* wg_ws    = (const float*)d_in[19];
    const float* wg_bs    = (const float*)d_in[20];
    const float* wg_g     = (const float*)d_in[21];
    const float* wg_beta  = (const float*)d_in[22];
    const float* mlp_w1   = (const float*)d_in[23];
    const float* mlp_b1   = (const float*)d_in[24];
    const float* mlp_w2   = (const float*)d_in[25];
    const float* mlp_b2   = (const float*)d_in[26];
    const float* reg_w1   = (const float*)d_in[27];
    const float* reg_b1   = (const float*)d_in[28];
    const float* reg_w2   = (const float*)d_in[29];
    const float* reg_b2   = (const float*)d_in[30];

    int Bn = in_sizes[0] / FD;
    float* out = (float*)d_out;
    float* wout = (out_size >= Bn * (FD + 1)) ? (out + Bn) : nullptr;

    cudaFuncSetAttribute(sel_mlp_kernel,
                         cudaFuncAttributeMaxDynamicSharedMemorySize,
                         SMEMB_FLOATS * (int)sizeof(float));

    int gridA = (Bn + 511) / 512;   // 256 threads x 2 rows
    var_grn_kernel<<<gridA, 256>>>(x_tab, emb_w, emb_b, grn_w1, grn_b1,
                                   grn_ws, grn_bs, grn_w2, grn_b2, grn_wg,
                                   grn_bg, grn_g, grn_beta, Bn);

    int gridB = (Bn + 255) / 256;   // 128 threads x 2 rows
    sel_mlp_kernel<<<gridB, 128, SMEMB_FLOATS * sizeof(float)>>>(
        wg_w1, wg_b1, wg_w2, wg_b2, wg_wgm, wg_bg, wg_ws, wg_bs, wg_g, wg_beta,
        mlp_w1, mlp_b1, mlp_w2, mlp_b2, reg_w1, reg_b1, reg_w2, reg_b2,
        out, wout, Bn);
}

// round 4
// speedup vs baseline: 1.4262x; 1.2003x over previous
#include <cuda_runtime.h>
#include <cuda_fp16.h>
#include <math.h>

#define FD 16
#define HD 16
#define ED 32
#define MAXB 131072

// fp16 transposed scratch: g_varh[chunk][row], chunk = f*2+hi (32 chunks),
// each uint4 = 8 half values (h = hi*8 .. hi*8+7). 64 MB total.
__device__ uint4 g_varh[(size_t)32 * MAXB];

__device__ __forceinline__ float fast_elu(float t) {
    return fmaxf(t, 0.f) + (__expf(fminf(t, 0.f)) - 1.f);
}
__device__ __forceinline__ float fast_sig(float x) {
    float t;
    asm("tanh.approx.f32 %0, %1;" : "=f"(t) : "f"(0.5f * x));
    return fmaf(0.5f, t, 0.5f);
}

// ---------------------------------------------------------------------------
// Kernel A: embedder-folded per-feature GRN + LayerNorm -> fp16 scratch.
// 128 threads/block, 2 rows/thread, <=128 regs (4 blocks/SM).
// ---------------------------------------------------------------------------
__global__ __launch_bounds__(128, 4) void var_grn_kernel(
    const float* __restrict__ x_tab,
    const float* __restrict__ emb_w, const float* __restrict__ emb_b,
    const float* __restrict__ w1g, const float* __restrict__ b1g,
    const float* __restrict__ wsg, const float* __restrict__ bsg,
    const float* __restrict__ w2, const float* __restrict__ b2,
    const float* __restrict__ wg, const float* __restrict__ bg,
    const float* __restrict__ gamma, const float* __restrict__ beta,
    int Bn)
{
    __shared__ float sA1[256], sC1[256], sAs[256], sCs[256];
    __shared__ float sW2[4096], sWg[4096];
    __shared__ float sB2[256], sBg[256], sG[256], sBe[256];
    int tid = threadIdx.x;
    // Fold Linear(1,E) embedder into GRN input/skip (each thread does 2 entries).
    for (int t = tid; t < 256; t += 128) {
        int f = t >> 4;
        const float* ew = emb_w + f * 32;
        const float* eb = emb_b + f * 32;
        const float* W1 = w1g + (size_t)t * 32;
        const float* Ws = wsg + (size_t)t * 32;
        float a1 = 0.f, c1 = 0.f, as_ = 0.f, cs = 0.f;
#pragma unroll
        for (int e = 0; e < 32; e++) {
            float we = ew[e], be = eb[e];
            a1  = fmaf(we, W1[e], a1);
            c1  = fmaf(be, W1[e], c1);
            as_ = fmaf(we, Ws[e], as_);
            cs  = fmaf(be, Ws[e], cs);
        }
        sA1[t] = a1;
        sC1[t] = c1 + b1g[t];
        sAs[t] = as_;
        sCs[t] = cs + bsg[t];
        sB2[t] = b2[t];  sBg[t] = bg[t];
        sG[t]  = gamma[t]; sBe[t] = beta[t];
    }
    for (int i = tid; i < 4096; i += 128) { sW2[i] = w2[i]; sWg[i] = wg[i]; }
    __syncthreads();

    int gid = blockIdx.x * 128 + tid;
    int r0 = gid * 2;
    if (r0 >= Bn) return;
    const float* x0 = x_tab + (size_t)r0 * 16;
    const float* x1 = x0 + 16;

#pragma unroll 1
    for (int f = 0; f < 16; f++) {
        int fb = f * 16;
        float xfa = __ldg(x0 + f);
        float xfb = __ldg(x1 + f);

        float ha[16], hb[16];
#pragma unroll
        for (int j = 0; j < 16; j++) {
            float a1 = sA1[fb + j], c1 = sC1[fb + j];
            ha[j] = fast_elu(fmaf(xfa, a1, c1));
            hb[j] = fast_elu(fmaf(xfb, a1, c1));
        }
        float oa[16], ob[16];
#pragma unroll
        for (int k = 0; k < 16; k++) {
            const float4* wr = (const float4*)&sW2[(fb + k) * 16];
            float A = sB2[fb + k], Bv = A;
#pragma unroll
            for (int q = 0; q < 4; q++) {
                float4 w = wr[q];
                A  = fmaf(ha[q*4+0], w.x, A);  A  = fmaf(ha[q*4+1], w.y, A);
                A  = fmaf(ha[q*4+2], w.z, A);  A  = fmaf(ha[q*4+3], w.w, A);
                Bv = fmaf(hb[q*4+0], w.x, Bv); Bv = fmaf(hb[q*4+1], w.y, Bv);
                Bv = fmaf(hb[q*4+2], w.z, Bv); Bv = fmaf(hb[q*4+3], w.w, Bv);
            }
            oa[k] = A; ob[k] = Bv;
        }
        float va[16], vb[16];
        float mua = 0.f, mub = 0.f;
#pragma unroll
        for (int j = 0; j < 16; j++) {
            const float4* wr = (const float4*)&sWg[(fb + j) * 16];
            float A = sBg[fb + j], Bv = A;
#pragma unroll
            for (int q = 0; q < 4; q++) {
                float4 w = wr[q];
                A  = fmaf(oa[q*4+0], w.x, A);  A  = fmaf(oa[q*4+1], w.y, A);
                A  = fmaf(oa[q*4+2], w.z, A);  A  = fmaf(oa[q*4+3], w.w, A);
                Bv = fmaf(ob[q*4+0], w.x, Bv); Bv = fmaf(ob[q*4+1], w.y, Bv);
                Bv = fmaf(ob[q*4+2], w.z, Bv); Bv = fmaf(ob[q*4+3], w.w, Bv);
            }
            float as_ = sAs[fb + j], cs = sCs[fb + j];
            float va_ = fmaf(oa[j], fast_sig(A),  fmaf(xfa, as_, cs));
            float vb_ = fmaf(ob[j], fast_sig(Bv), fmaf(xfb, as_, cs));
            va[j] = va_; vb[j] = vb_;
            mua += va_;  mub += vb_;
        }
        mua *= 0.0625f; mub *= 0.0625f;
        float vara = 0.f, varb = 0.f;
#pragma unroll
        for (int j = 0; j < 16; j++) {
            float da = va[j] - mua; vara = fmaf(da, da, vara);
            float db = vb[j] - mub; varb = fmaf(db, db, varb);
        }
        float rsa = rsqrtf(fmaf(vara, 0.0625f, 1e-5f));
        float rsb = rsqrtf(fmaf(varb, 0.0625f, 1e-5f));
        // Normalize, convert to fp16, store 2x uint4 per row.
#pragma unroll
        for (int hi = 0; hi < 2; hi++) {
            uint4 pa, pb;
            __half2* qa = reinterpret_cast<__half2*>(&pa);
            __half2* qb = reinterpret_cast<__half2*>(&pb);
#pragma unroll
            for (int p = 0; p < 4; p++) {
                int j = hi * 8 + p * 2;
                float g0 = sG[fb+j], g1 = sG[fb+j+1];
                float e0 = sBe[fb+j], e1 = sBe[fb+j+1];
                float ya0 = (va[j]   - mua) * rsa * g0 + e0;
                float ya1 = (va[j+1] - mua) * rsa * g1 + e1;
                float yb0 = (vb[j]   - mub) * rsb * g0 + e0;
                float yb1 = (vb[j+1] - mub) * rsb * g1 + e1;
                qa[p] = __floats2half2_rn(ya0, ya1);
                qb[p] = __floats2half2_rn(yb0, yb1);
            }
            size_t base = (size_t)(f * 2 + hi) * Bn + r0;
            g_varh[base]     = pa;
            g_varh[base + 1] = pb;
        }
    }
}

// ---------------------------------------------------------------------------
// Kernel B: weight GRN + softmax + selection + MLP + regressor.
// 128 threads/block, 2 rows/thread, chunked MLP, <=128 regs (4 blocks/SM).
// ---------------------------------------------------------------------------
#define OFF_W1   0
#define OFF_WS   4096
#define OFF_W2   8192
#define OFF_WGG  8448
#define OFF_MW1  8704
#define OFF_MW2  9728
#define OFF_RW1  11776
#define OFF_B1   13824
#define OFF_B2F  13840
#define OFF_BGG  13856
#define OFF_BS   13872
#define OFF_G    13888
#define OFF_BE   13904
#define OFF_MB1  13920
#define OFF_MB2  13984
#define OFF_RB1  14016
#define OFF_RW2  14080
#define OFF_RB2  14144
#define SMEMB_FLOATS 14148

__device__ __forceinline__ void head_mlp_row(
    const float* __restrict__ s, float* hw, float* skw,
    int row, float* __restrict__ out, float* __restrict__ wout, int Bn)
{
#pragma unroll
    for (int j = 0; j < 16; j++) {
        hw[j]  = fast_elu(hw[j] + s[OFF_B1 + j]);
        skw[j] += s[OFF_BS + j];
    }
    float ow[16];
#pragma unroll
    for (int j = 0; j < 16; j++) {
        const float4* wr = (const float4*)&s[OFF_W2 + j * 16];
        float a = s[OFF_B2F + j];
#pragma unroll
        for (int q = 0; q < 4; q++) {
            float4 w = wr[q];
            a = fmaf(hw[q*4+0], w.x, a); a = fmaf(hw[q*4+1], w.y, a);
            a = fmaf(hw[q*4+2], w.z, a); a = fmaf(hw[q*4+3], w.w, a);
        }
        ow[j] = a;
    }
    float l[16];
    float mu = 0.f;
#pragma unroll
    for (int i = 0; i < 16; i++) {
        const float4* wr = (const float4*)&s[OFF_WGG + i * 16];
        float g = s[OFF_BGG + i];
#pragma unroll
        for (int q = 0; q < 4; q++) {
            float4 w = wr[q];
            g = fmaf(ow[q*4+0], w.x, g); g = fmaf(ow[q*4+1], w.y, g);
            g = fmaf(ow[q*4+2], w.z, g); g = fmaf(ow[q*4+3], w.w, g);
        }
        float li = fmaf(ow[i], fast_sig(g), skw[i]);
        l[i] = li; mu += li;
    }
    mu *= 0.0625f;
    float varv = 0.f;
#pragma unroll
    for (int i = 0; i < 16; i++) { float d = l[i] - mu; varv = fmaf(d, d, varv); }
    float rs = rsqrtf(fmaf(varv, 0.0625f, 1e-5f));
    float wt[16];
    float mx = -1e30f;
#pragma unroll
    for (int i = 0; i < 16; i++) {
        float li = (l[i] - mu) * rs * s[OFF_G + i] + s[OFF_BE + i];
        wt[i] = li;
        mx = fmaxf(mx, li);
    }
    float sum = 0.f;
#pragma unroll
    for (int i = 0; i < 16; i++) { wt[i] = __expf(wt[i] - mx); sum += wt[i]; }
    float inv = 1.f / sum;
#pragma unroll
    for (int i = 0; i < 16; i++) wt[i] *= inv;

    if (wout) {
        float* wo = wout + (size_t)row * 16;
#pragma unroll
        for (int q = 0; q < 4; q++) {
            float4 st; st.x = wt[q*4]; st.y = wt[q*4+1]; st.z = wt[q*4+2]; st.w = wt[q*4+3];
            *(float4*)(wo + q * 4) = st;
        }
    }

    // sel[h] = sum_f v[f,h] * wt[f]  (fp16 re-read, L1-hot)
    float sel[16];
#pragma unroll
    for (int h = 0; h < 16; h++) sel[h] = 0.f;
#pragma unroll 1
    for (int f = 0; f < 16; f++) {
        float wf = wt[f];
#pragma unroll
        for (int hi = 0; hi < 2; hi++) {
            uint4 t = g_varh[(size_t)(f * 2 + hi) * Bn + row];
            const __half2* ph = reinterpret_cast<const __half2*>(&t);
#pragma unroll
            for (int p = 0; p < 4; p++) {
                float2 v2 = __half22float2(ph[p]);
                int j = hi * 8 + p * 2;
                sel[j]   = fmaf(v2.x, wf, sel[j]);
                sel[j+1] = fmaf(v2.y, wf, sel[j+1]);
            }
        }
    }

    // MLP 16->64->32 (chunked: m1 in 16-wide chunks accumulated into m2[32])
    float m2[32];
#pragma unroll
    for (int i = 0; i < 32; i++) m2[i] = s[OFF_MB2 + i];
#pragma unroll 1
    for (int c = 0; c < 4; c++) {
        float m1c[16];
#pragma unroll
        for (int k = 0; k < 16; k++) {
            int i = c * 16 + k;
            const float4* wr = (const float4*)&s[OFF_MW1 + i * 16];
            float a = s[OFF_MB1 + i];
#pragma unroll
            for (int q = 0; q < 4; q++) {
                float4 w = wr[q];
                a = fmaf(sel[q*4+0], w.x, a); a = fmaf(sel[q*4+1], w.y, a);
                a = fmaf(sel[q*4+2], w.z, a); a = fmaf(sel[q*4+3], w.w, a);
            }
            m1c[k] = fmaxf(a, 0.f);
        }
#pragma unroll
        for (int i = 0; i < 32; i++) {
            const float4* wr = (const float4*)&s[OFF_MW2 + i * 64 + c * 16];
            float a = m2[i];
#pragma unroll
            for (int q = 0; q < 4; q++) {
                float4 w = wr[q];
                a = fmaf(m1c[q*4+0], w.x, a); a = fmaf(m1c[q*4+1], w.y, a);
                a = fmaf(m1c[q*4+2], w.z, a); a = fmaf(m1c[q*4+3], w.w, a);
            }
            m2[i] = a;
        }
    }
#pragma unroll
    for (int i = 0; i < 32; i++) m2[i] = fmaxf(m2[i], 0.f);

    // Regressor 32->64->1 (final layer fused into running dot)
    float acc_out = s[OFF_RB2];
#pragma unroll 4
    for (int i = 0; i < 64; i++) {
        const float4* wr = (const float4*)&s[OFF_RW1 + i * 32];
        float a = s[OFF_RB1 + i];
#pragma unroll
        for (int q = 0; q < 8; q++) {
            float4 w = wr[q];
            a = fmaf(m2[q*4+0], w.x, a); a = fmaf(m2[q*4+1], w.y, a);
            a = fmaf(m2[q*4+2], w.z, a); a = fmaf(m2[q*4+3], w.w, a);
        }
        acc_out = fmaf(fmaxf(a, 0.f), s[OFF_RW2 + i], acc_out);
    }
    out[row] = acc_out;
}

__global__ __launch_bounds__(128, 4) void sel_mlp_kernel(
    const float* __restrict__ wg_w1, const float* __restrict__ wg_b1,
    const float* __restrict__ wg_w2, const float* __restrict__ wg_b2,
    const float* __restrict__ wg_wgm, const float* __restrict__ wg_bg,
    const float* __restrict__ wg_ws, const float* __restrict__ wg_bs,
    const float* __restrict__ wg_g, const float* __restrict__ wg_beta,
    const float* __restrict__ mlp_w1, const float* __restrict__ mlp_b1,
    const float* __restrict__ mlp_w2, const float* __restrict__ mlp_b2,
    const float* __restrict__ reg_w1, const float* __restrict__ reg_b1,
    const float* __restrict__ reg_w2, const float* __restrict__ reg_b2,
    float* __restrict__ out, float* __restrict__ wout, int Bn)
{
    extern __shared__ float s[];
    int tid = threadIdx.x;
    for (int i = tid; i < 4096; i += 128) { s[OFF_W1+i] = wg_w1[i]; s[OFF_WS+i] = wg_ws[i]; }
    for (int i = tid; i < 2048; i += 128) { s[OFF_MW2+i] = mlp_w2[i]; s[OFF_RW1+i] = reg_w1[i]; }
    for (int i = tid; i < 1024; i += 128) s[OFF_MW1+i] = mlp_w1[i];
    for (int i = tid; i < 256; i += 128) { s[OFF_W2+i] = wg_w2[i]; s[OFF_WGG+i] = wg_wgm[i]; }
    if (tid < 64) { s[OFF_MB1+tid] = mlp_b1[tid]; s[OFF_RB1+tid] = reg_b1[tid]; s[OFF_RW2+tid] = reg_w2[tid]; }
    if (tid < 32) s[OFF_MB2+tid] = mlp_b2[tid];
    if (tid < 16) {
        s[OFF_B1+tid]  = wg_b1[tid];  s[OFF_B2F+tid] = wg_b2[tid];
        s[OFF_BGG+tid] = wg_bg[tid];  s[OFF_BS+tid]  = wg_bs[tid];
        s[OFF_G+tid]   = wg_g[tid];   s[OFF_BE+tid]  = wg_beta[tid];
    }
    if (tid == 0) s[OFF_RB2] = reg_b2[0];
    __syncthreads();

    int gid = blockIdx.x * 128 + tid;
    int r0 = gid * 2;
    if (r0 >= Bn) return;

    float hwa[16], hwb[16], ska[16], skb[16];
#pragma unroll
    for (int j = 0; j < 16; j++) { hwa[j]=0.f; hwb[j]=0.f; ska[j]=0.f; skb[j]=0.f; }

#pragma unroll 1
    for (int f = 0; f < 16; f++) {
        float va[16], vb[16];
#pragma unroll
        for (int hi = 0; hi < 2; hi++) {
            size_t base = (size_t)(f * 2 + hi) * Bn + r0;
            uint4 ta = g_varh[base];
            uint4 tb = g_varh[base + 1];
            const __half2* pa = reinterpret_cast<const __half2*>(&ta);
            const __half2* pb = reinterpret_cast<const __half2*>(&tb);
#pragma unroll
            for (int p = 0; p < 4; p++) {
                float2 fa = __half22float2(pa[p]);
                float2 fb2 = __half22float2(pb[p]);
                int j = hi * 8 + p * 2;
                va[j] = fa.x; va[j+1] = fa.y;
                vb[j] = fb2.x; vb[j+1] = fb2.y;
            }
        }
#pragma unroll
        for (int j = 0; j < 16; j++) {
            const float4* wa = (const float4*)&s[OFF_W1 + j * 256 + f * 16];
            const float4* wb = (const float4*)&s[OFF_WS + j * 256 + f * 16];
            float Aa = hwa[j], Ab = hwb[j], Sa = ska[j], Sb = skb[j];
#pragma unroll
            for (int q = 0; q < 4; q++) {
                float4 w = wa[q];
                Aa = fmaf(va[q*4+0], w.x, Aa); Aa = fmaf(va[q*4+1], w.y, Aa);
                Aa = fmaf(va[q*4+2], w.z, Aa); Aa = fmaf(va[q*4+3], w.w, Aa);
                Ab = fmaf(vb[q*4+0], w.x, Ab); Ab = fmaf(vb[q*4+1], w.y, Ab);
                Ab = fmaf(vb[q*4+2], w.z, Ab); Ab = fmaf(vb[q*4+3], w.w, Ab);
                float4 v2 = wb[q];
                Sa = fmaf(va[q*4+0], v2.x, Sa); Sa = fmaf(va[q*4+1], v2.y, Sa);
                Sa = fmaf(va[q*4+2], v2.z, Sa); Sa = fmaf(va[q*4+3], v2.w, Sa);
                Sb = fmaf(vb[q*4+0], v2.x, Sb); Sb = fmaf(vb[q*4+1], v2.y, Sb);
                Sb = fmaf(vb[q*4+2], v2.z, Sb); Sb = fmaf(vb[q*4+3], v2.w, Sb);
            }
            hwa[j] = Aa; hwb[j] = Ab; ska[j] = Sa; skb[j] = Sb;
        }
    }
    head_mlp_row(s, hwa, ska, r0,     out, wout, Bn);
    head_mlp_row(s, hwb, skb, r0 + 1, out, wout, Bn);
}

// ---------------------------------------------------------------------------
extern "C" void kernel_launch(void* const* d_in, const int* in_sizes, int n_in,
                              void* d_out, int out_size) {
    const float* x_tab    = (const float*)d_in[0];
    const float* emb_w    = (const float*)d_in[1];
    const float* emb_b    = (const float*)d_in[2];
    const float* grn_w1   = (const float*)d_in[3];
    const float* grn_b1   = (const float*)d_in[4];
    const float* grn_w2   = (const float*)d_in[5];
    const float* grn_b2   = (const float*)d_in[6];
    const float* grn_wg   = (const float*)d_in[7];
    const float* grn_bg   = (const float*)d_in[8];
    const float* grn_ws   = (const float*)d_in[9];
    const float* grn_bs   = (const float*)d_in[10];
    const float* grn_g    = (const float*)d_in[11];
    const float* grn_beta = (const float*)d_in[12];
    const float* wg_w1    = (const float*)d_in[13];
    const float* wg_b1    = (const float*)d_in[14];
    const float* wg_w2    = (const float*)d_in[15];
    const float* wg_b2    = (const float*)d_in[16];
    const float* wg_wgm   = (const float*)d_in[17];
    const float* wg_bg    = (const float*)d_in[18];
    const float* wg_ws    = (const float*)d_in[19];
    const float* wg_bs    = (const float*)d_in[20];
    const float* wg_g     = (const float*)d_in[21];
    const float* wg_beta  = (const float*)d_in[22];
    const float* mlp_w1   = (const float*)d_in[23];
    const float* mlp_b1   = (const float*)d_in[24];
    const float* mlp_w2   = (const float*)d_in[25];
    const float* mlp_b2   = (const float*)d_in[26];
    const float* reg_w1   = (const float*)d_in[27];
    const float* reg_b1   = (const float*)d_in[28];
    const float* reg_w2   = (const float*)d_in[29];
    const float* reg_b2   = (const float*)d_in[30];

    int Bn = in_sizes[0] / FD;
    float* out = (float*)d_out;
    float* wout = (out_size >= Bn * (FD + 1)) ? (out + Bn) : nullptr;

    cudaFuncSetAttribute(sel_mlp_kernel,
                         cudaFuncAttributeMaxDynamicSharedMemorySize,
                         SMEMB_FLOATS * (int)sizeof(float));

    int gridA = (Bn + 255) / 256;   // 128 threads x 2 rows
    var_grn_kernel<<<gridA, 128>>>(x_tab, emb_w, emb_b, grn_w1, grn_b1,
                                   grn_ws, grn_bs, grn_w2, grn_b2, grn_wg,
                                   grn_bg, grn_g, grn_beta, Bn);

    int gridB = (Bn + 255) / 256;   // 128 threads x 2 rows
    sel_mlp_kernel<<<gridB, 128, SMEMB_FLOATS * sizeof(float)>>>(
        wg_w1, wg_b1, wg_w2, wg_b2, wg_wgm, wg_bg, wg_ws, wg_bs, wg_g, wg_beta,
        mlp_w1, mlp_b1, mlp_w2, mlp_b2, reg_w1, reg_b1, reg_w2, reg_b2,
        out, wout, Bn);
}

// round 6
// speedup vs baseline: 1.8195x; 1.2757x over previous
#include <cuda_runtime.h>
#include <cuda_fp16.h>
#include <math.h>

#define FD 16
#define HD 16
#define MAXB 131072

// fp16 transposed scratch: g_varh[chunk][row], chunk = f*2+hi (32 chunks),
// each uint4 = 8 half values. 64 MB total.
__device__ uint4 g_varh[(size_t)32 * MAXB];

typedef unsigned long long u64t;

__device__ __forceinline__ float fast_elu(float t) {
    return fmaxf(t, 0.f) + (__expf(fminf(t, 0.f)) - 1.f);
}
__device__ __forceinline__ float fast_sig(float x) {
    float t;
    asm("tanh.approx.f32 %0, %1;" : "=f"(t) : "f"(0.5f * x));
    return fmaf(0.5f, t, 0.5f);
}
// ---- packed f32x2 helpers (Blackwell) ----
__device__ __forceinline__ u64t pk2(float lo, float hi) {
    u64t r;
    asm("mov.b64 %0, {%1, %2};" : "=l"(r) : "r"(__float_as_uint(lo)), "r"(__float_as_uint(hi)));
    return r;
}
__device__ __forceinline__ u64t fma2(u64t a, u64t b, u64t c) {
    u64t d;
    asm("fma.rn.f32x2 %0, %1, %2, %3;" : "=l"(d) : "l"(a), "l"(b), "l"(c));
    return d;
}
__device__ __forceinline__ float hadd2(u64t v) {
    unsigned lo, hi;
    asm("mov.b64 {%0, %1}, %2;" : "=r"(lo), "=r"(hi) : "l"(v));
    return __uint_as_float(lo) + __uint_as_float(hi);
}
__device__ __forceinline__ u64t h2pk(__half2 h) {
    float2 f = __half22float2(h);
    return pk2(f.x, f.y);
}

// ---------------------------------------------------------------------------
// Kernel A: embedder-folded per-feature GRN + LayerNorm -> fp16 scratch.
// 128 threads/block, 2 rows/thread, f32x2 packed matvecs.
// ---------------------------------------------------------------------------
__global__ __launch_bounds__(128, 4) void var_grn_kernel(
    const float* __restrict__ x_tab,
    const float* __restrict__ emb_w, const float* __restrict__ emb_b,
    const float* __restrict__ w1g, const float* __restrict__ b1g,
    const float* __restrict__ wsg, const float* __restrict__ bsg,
    const float* __restrict__ w2, const float* __restrict__ b2,
    const float* __restrict__ wg, const float* __restrict__ bg,
    const float* __restrict__ gamma, const float* __restrict__ beta,
    int Bn)
{
    __shared__ float sA1[256], sC1[256], sAs[256], sCs[256];
    __shared__ float sW2[4096], sWg[4096];
    __shared__ float sB2[256], sBg[256], sG[256], sBe[256];
    int tid = threadIdx.x;
    for (int t = tid; t < 256; t += 128) {
        int f = t >> 4;
        const float* ew = emb_w + f * 32;
        const float* eb = emb_b + f * 32;
        const float* W1 = w1g + (size_t)t * 32;
        const float* Ws = wsg + (size_t)t * 32;
        float a1 = 0.f, c1 = 0.f, as_ = 0.f, cs = 0.f;
#pragma unroll
        for (int e = 0; e < 32; e++) {
            float we = ew[e], be = eb[e];
            a1  = fmaf(we, W1[e], a1);
            c1  = fmaf(be, W1[e], c1);
            as_ = fmaf(we, Ws[e], as_);
            cs  = fmaf(be, Ws[e], cs);
        }
        sA1[t] = a1;
        sC1[t] = c1 + b1g[t];
        sAs[t] = as_;
        sCs[t] = cs + bsg[t];
        sB2[t] = b2[t];  sBg[t] = bg[t];
        sG[t]  = gamma[t]; sBe[t] = beta[t];
    }
    for (int i = tid; i < 4096; i += 128) { sW2[i] = w2[i]; sWg[i] = wg[i]; }
    __syncthreads();

    int gid = blockIdx.x * 128 + tid;
    int r0 = gid * 2;
    if (r0 >= Bn) return;
    const float* x0 = x_tab + (size_t)r0 * 16;
    const float* x1 = x0 + 16;

#pragma unroll 1
    for (int f = 0; f < 16; f++) {
        int fb = f * 16;
        float xfa = __ldg(x0 + f);
        float xfb = __ldg(x1 + f);

        // h = elu(x_f * A1 + C1), packed into h-pairs per row
        u64t hap[8], hbp[8];
#pragma unroll
        for (int p = 0; p < 8; p++) {
            float a0 = sA1[fb + 2*p],   c0 = sC1[fb + 2*p];
            float a1 = sA1[fb + 2*p+1], c1 = sC1[fb + 2*p+1];
            hap[p] = pk2(fast_elu(fmaf(xfa, a0, c0)), fast_elu(fmaf(xfa, a1, c1)));
            hbp[p] = pk2(fast_elu(fmaf(xfb, a0, c0)), fast_elu(fmaf(xfb, a1, c1)));
        }
        // o = h @ w2[f].T + b2[f], built directly into packed pairs
        u64t oap[8], obp[8];
#pragma unroll
        for (int p = 0; p < 8; p++) {
            u64t A0 = 0ull, A1 = 0ull, B0 = 0ull, B1 = 0ull;
            const ulonglong2* w0 = (const ulonglong2*)&sW2[(fb + 2*p) * 16];
            const ulonglong2* w1 = (const ulonglong2*)&sW2[(fb + 2*p+1) * 16];
#pragma unroll
            for (int q = 0; q < 4; q++) {
                ulonglong2 wu0 = w0[q];
                ulonglong2 wu1 = w1[q];
                A0 = fma2(hap[2*q], wu0.x, A0); A0 = fma2(hap[2*q+1], wu0.y, A0);
                B0 = fma2(hbp[2*q], wu0.x, B0); B0 = fma2(hbp[2*q+1], wu0.y, B0);
                A1 = fma2(hap[2*q], wu1.x, A1); A1 = fma2(hap[2*q+1], wu1.y, A1);
                B1 = fma2(hbp[2*q], wu1.x, B1); B1 = fma2(hbp[2*q+1], wu1.y, B1);
            }
            float b0 = sB2[fb + 2*p], b1 = sB2[fb + 2*p+1];
            oap[p] = pk2(b0 + hadd2(A0), b1 + hadd2(A1));
            obp[p] = pk2(b0 + hadd2(B0), b1 + hadd2(B1));
        }
        // gate + skip, accumulate LN mean (process j in pairs)
        float va[16], vb[16];
        float mua = 0.f, mub = 0.f;
#pragma unroll
        for (int p = 0; p < 8; p++) {
            u64t A0 = 0ull, A1 = 0ull, B0 = 0ull, B1 = 0ull;
            const ulonglong2* w0 = (const ulonglong2*)&sWg[(fb + 2*p) * 16];
            const ulonglong2* w1 = (const ulonglong2*)&sWg[(fb + 2*p+1) * 16];
#pragma unroll
            for (int q = 0; q < 4; q++) {
                ulonglong2 wu0 = w0[q];
                ulonglong2 wu1 = w1[q];
                A0 = fma2(oap[2*q], wu0.x, A0); A0 = fma2(oap[2*q+1], wu0.y, A0);
                B0 = fma2(obp[2*q], wu0.x, B0); B0 = fma2(obp[2*q+1], wu0.y, B0);
                A1 = fma2(oap[2*q], wu1.x, A1); A1 = fma2(oap[2*q+1], wu1.y, A1);
                B1 = fma2(obp[2*q], wu1.x, B1); B1 = fma2(obp[2*q+1], wu1.y, B1);
            }
            unsigned olo, ohi;
            asm("mov.b64 {%0, %1}, %2;" : "=r"(olo), "=r"(ohi) : "l"(oap[p]));
            float oa0 = __uint_as_float(olo), oa1 = __uint_as_float(ohi);
            asm("mov.b64 {%0, %1}, %2;" : "=r"(olo), "=r"(ohi) : "l"(obp[p]));
            float ob0 = __uint_as_float(olo), ob1 = __uint_as_float(ohi);

            int j0 = fb + 2*p, j1 = fb + 2*p + 1;
            float ga0 = sBg[j0] + hadd2(A0), ga1 = sBg[j1] + hadd2(A1);
            float gb0 = sBg[j0] + hadd2(B0), gb1 = sBg[j1] + hadd2(B1);
            float v00 = fmaf(oa0, fast_sig(ga0), fmaf(xfa, sAs[j0], sCs[j0]));
            float v01 = fmaf(oa1, fast_sig(ga1), fmaf(xfa, sAs[j1], sCs[j1]));
            float v10 = fmaf(ob0, fast_sig(gb0), fmaf(xfb, sAs[j0], sCs[j0]));
            float v11 = fmaf(ob1, fast_sig(gb1), fmaf(xfb, sAs[j1], sCs[j1]));
            va[2*p] = v00; va[2*p+1] = v01;
            vb[2*p] = v10; vb[2*p+1] = v11;
            mua += v00 + v01; mub += v10 + v11;
        }
        mua *= 0.0625f; mub *= 0.0625f;
        float vara = 0.f, varb = 0.f;
#pragma unroll
        for (int j = 0; j < 16; j++) {
            float da = va[j] - mua; vara = fmaf(da, da, vara);
            float db = vb[j] - mub; varb = fmaf(db, db, varb);
        }
        float rsa = rsqrtf(fmaf(vara, 0.0625f, 1e-5f));
        float rsb = rsqrtf(fmaf(varb, 0.0625f, 1e-5f));
#pragma unroll
        for (int hi = 0; hi < 2; hi++) {
            uint4 pa, pb;
            __half2* qa = reinterpret_cast<__half2*>(&pa);
            __half2* qb = reinterpret_cast<__half2*>(&pb);
#pragma unroll
            for (int p = 0; p < 4; p++) {
                int j = hi * 8 + p * 2;
                float g0 = sG[fb+j], g1 = sG[fb+j+1];
                float e0 = sBe[fb+j], e1 = sBe[fb+j+1];
                qa[p] = __floats2half2_rn((va[j]   - mua) * rsa * g0 + e0,
                                          (va[j+1] - mua) * rsa * g1 + e1);
                qb[p] = __floats2half2_rn((vb[j]   - mub) * rsb * g0 + e0,
                                          (vb[j+1] - mub) * rsb * g1 + e1);
            }
            size_t base = (size_t)(f * 2 + hi) * Bn + r0;
            g_varh[base]     = pa;
            g_varh[base + 1] = pb;
        }
    }
}

// ---------------------------------------------------------------------------
// Kernel B: weight GRN + softmax + selection + MLP + regressor.
// 128 threads/block, 1 row/thread, f32x2 packed throughout.
// ---------------------------------------------------------------------------
#define OFF_W1   0
#define OFF_WS   4096
#define OFF_W2   8192
#define OFF_WGG  8448
#define OFF_MW1  8704
#define OFF_MW2  9728
#define OFF_RW1  11776
#define OFF_B1   13824
#define OFF_B2F  13840
#define OFF_BGG  13856
#define OFF_BS   13872
#define OFF_G    13888
#define OFF_BE   13904
#define OFF_MB1  13920
#define OFF_MB2  13984
#define OFF_RB1  14016
#define OFF_RW2  14080
#define OFF_RB2  14144
#define SMEMB_FLOATS 14148

__global__ __launch_bounds__(128, 4) void sel_mlp_kernel(
    const float* __restrict__ wg_w1, const float* __restrict__ wg_b1,
    const float* __restrict__ wg_w2, const float* __restrict__ wg_b2,
    const float* __restrict__ wg_wgm, const float* __restrict__ wg_bg,
    const float* __restrict__ wg_ws, const float* __restrict__ wg_bs,
    const float* __restrict__ wg_g, const float* __restrict__ wg_beta,
    const float* __restrict__ mlp_w1, const float* __restrict__ mlp_b1,
    const float* __restrict__ mlp_w2, const float* __restrict__ mlp_b2,
    const float* __restrict__ reg_w1, const float* __restrict__ reg_b1,
    const float* __restrict__ reg_w2, const float* __restrict__ reg_b2,
    float* __restrict__ out, float* __restrict__ wout, int Bn)
{
    extern __shared__ float s[];
    int tid = threadIdx.x;
    for (int i = tid; i < 4096; i += 128) { s[OFF_W1+i] = wg_w1[i]; s[OFF_WS+i] = wg_ws[i]; }
    for (int i = tid; i < 2048; i += 128) { s[OFF_MW2+i] = mlp_w2[i]; s[OFF_RW1+i] = reg_w1[i]; }
    for (int i = tid; i < 1024; i += 128) s[OFF_MW1+i] = mlp_w1[i];
    for (int i = tid; i < 256; i += 128) { s[OFF_W2+i] = wg_w2[i]; s[OFF_WGG+i] = wg_wgm[i]; }
    if (tid < 64) { s[OFF_MB1+tid] = mlp_b1[tid]; s[OFF_RB1+tid] = reg_b1[tid]; s[OFF_RW2+tid] = reg_w2[tid]; }
    if (tid < 32) s[OFF_MB2+tid] = mlp_b2[tid];
    if (tid < 16) {
        s[OFF_B1+tid]  = wg_b1[tid];  s[OFF_B2F+tid] = wg_b2[tid];
        s[OFF_BGG+tid] = wg_bg[tid];  s[OFF_BS+tid]  = wg_bs[tid];
        s[OFF_G+tid]   = wg_g[tid];   s[OFF_BE+tid]  = wg_beta[tid];
    }
    if (tid == 0) s[OFF_RB2] = reg_b2[0];
    __syncthreads();

    int row = blockIdx.x * 128 + tid;
    if (row >= Bn) return;

    // ---- main contraction: hw/skw (even/odd partial pairs) ----
    u64t hw2[16], sk2[16];
#pragma unroll
    for (int j = 0; j < 16; j++) { hw2[j] = 0ull; sk2[j] = 0ull; }

#pragma unroll 1
    for (int f = 0; f < 16; f++) {
        u64t v2[8];
#pragma unroll
        for (int hi = 0; hi < 2; hi++) {
            uint4 t = g_varh[(size_t)(f * 2 + hi) * Bn + row];
            const __half2* ph = reinterpret_cast<const __half2*>(&t);
#pragma unroll
            for (int p = 0; p < 4; p++) v2[hi*4 + p] = h2pk(ph[p]);
        }
#pragma unroll
        for (int j = 0; j < 16; j++) {
            const ulonglong2* wa = (const ulonglong2*)&s[OFF_W1 + j * 256 + f * 16];
            const ulonglong2* wb = (const ulonglong2*)&s[OFF_WS + j * 256 + f * 16];
            u64t A = hw2[j], S = sk2[j];
#pragma unroll
            for (int q = 0; q < 4; q++) {
                ulonglong2 w1 = wa[q];
                A = fma2(v2[2*q], w1.x, A); A = fma2(v2[2*q+1], w1.y, A);
                ulonglong2 w2v = wb[q];
                S = fma2(v2[2*q], w2v.x, S); S = fma2(v2[2*q+1], w2v.y, S);
            }
            hw2[j] = A; sk2[j] = S;
        }
    }
    // collapse partials, elu / bias
    u64t hwp[8];
    float skw[16];
#pragma unroll
    for (int p = 0; p < 8; p++) {
        float h0 = fast_elu(hadd2(hw2[2*p])   + s[OFF_B1 + 2*p]);
        float h1 = fast_elu(hadd2(hw2[2*p+1]) + s[OFF_B1 + 2*p+1]);
        hwp[p] = pk2(h0, h1);
        skw[2*p]   = hadd2(sk2[2*p])   + s[OFF_BS + 2*p];
        skw[2*p+1] = hadd2(sk2[2*p+1]) + s[OFF_BS + 2*p+1];
    }
    // ow = hw @ wg_w2.T + b2  (packed pairs)
    u64t owp[8];
    float ow[16];
#pragma unroll
    for (int p = 0; p < 8; p++) {
        const ulonglong2* w0 = (const ulonglong2*)&s[OFF_W2 + (2*p) * 16];
        const ulonglong2* w1 = (const ulonglong2*)&s[OFF_W2 + (2*p+1) * 16];
        u64t A0 = 0ull, A1 = 0ull;
#pragma unroll
        for (int q = 0; q < 4; q++) {
            ulonglong2 u0 = w0[q], u1 = w1[q];
            A0 = fma2(hwp[2*q], u0.x, A0); A0 = fma2(hwp[2*q+1], u0.y, A0);
            A1 = fma2(hwp[2*q], u1.x, A1); A1 = fma2(hwp[2*q+1], u1.y, A1);
        }
        float o0 = s[OFF_B2F + 2*p]   + hadd2(A0);
        float o1 = s[OFF_B2F + 2*p+1] + hadd2(A1);
        ow[2*p] = o0; ow[2*p+1] = o1;
        owp[p] = pk2(o0, o1);
    }
    // gate + skip + LN
    float l[16];
    float mu = 0.f;
#pragma unroll
    for (int p = 0; p < 8; p++) {
        const ulonglong2* w0 = (const ulonglong2*)&s[OFF_WGG + (2*p) * 16];
        const ulonglong2* w1 = (const ulonglong2*)&s[OFF_WGG + (2*p+1) * 16];
        u64t A0 = 0ull, A1 = 0ull;
#pragma unroll
        for (int q = 0; q < 4; q++) {
            ulonglong2 u0 = w0[q], u1 = w1[q];
            A0 = fma2(owp[2*q], u0.x, A0); A0 = fma2(owp[2*q+1], u0.y, A0);
            A1 = fma2(owp[2*q], u1.x, A1); A1 = fma2(owp[2*q+1], u1.y, A1);
        }
        float g0 = s[OFF_BGG + 2*p]   + hadd2(A0);
        float g1 = s[OFF_BGG + 2*p+1] + hadd2(A1);
        float l0 = fmaf(ow[2*p],   fast_sig(g0), skw[2*p]);
        float l1 = fmaf(ow[2*p+1], fast_sig(g1), skw[2*p+1]);
        l[2*p] = l0; l[2*p+1] = l1;
        mu += l0 + l1;
    }
    mu *= 0.0625f;
    float varv = 0.f;
#pragma unroll
    for (int i = 0; i < 16; i++) { float d = l[i] - mu; varv = fmaf(d, d, varv); }
    float rs = rsqrtf(fmaf(varv, 0.0625f, 1e-5f));
    float wt[16];
    float mx = -1e30f;
#pragma unroll
    for (int i = 0; i < 16; i++) {
        float li = (l[i] - mu) * rs * s[OFF_G + i] + s[OFF_BE + i];
        wt[i] = li;
        mx = fmaxf(mx, li);
    }
    float sum = 0.f;
#pragma unroll
    for (int i = 0; i < 16; i++) { wt[i] = __expf(wt[i] - mx); sum += wt[i]; }
    float inv = 1.f / sum;
#pragma unroll
    for (int i = 0; i < 16; i++) wt[i] *= inv;

    if (wout) {
        float* wo = wout + (size_t)row * 16;
#pragma unroll
        for (int q = 0; q < 4; q++) {
            float4 st; st.x = wt[q*4]; st.y = wt[q*4+1]; st.z = wt[q*4+2]; st.w = wt[q*4+3];
            *(float4*)(wo + q * 4) = st;
        }
    }

    // sel[h] = sum_f v[f,h]*wt[f]  -> packed pairs sel2[8]
    u64t sel2[8];
#pragma unroll
    for (int p = 0; p < 8; p++) sel2[p] = 0ull;
#pragma unroll 1
    for (int f = 0; f < 16; f++) {
        u64t wf2 = pk2(wt[f], wt[f]);
#pragma unroll
        for (int hi = 0; hi < 2; hi++) {
            uint4 t = g_varh[(size_t)(f * 2 + hi) * Bn + row];
            const __half2* ph = reinterpret_cast<const __half2*>(&t);
#pragma unroll
            for (int p = 0; p < 4; p++)
                sel2[hi*4+p] = fma2(h2pk(ph[p]), wf2, sel2[hi*4+p]);
        }
    }

    // MLP 16->64->32 (chunked) with packed pairs
    float m2[32];
#pragma unroll
    for (int i = 0; i < 32; i++) m2[i] = s[OFF_MB2 + i];
#pragma unroll 1
    for (int c = 0; c < 4; c++) {
        u64t m1p[8];
#pragma unroll
        for (int k = 0; k < 8; k++) {
            int i0 = c * 16 + 2*k;
            const ulonglong2* w0 = (const ulonglong2*)&s[OFF_MW1 + i0 * 16];
            const ulonglong2* w1 = (const ulonglong2*)&s[OFF_MW1 + (i0+1) * 16];
            u64t A0 = 0ull, A1 = 0ull;
#pragma unroll
            for (int q = 0; q < 4; q++) {
                ulonglong2 u0 = w0[q], u1 = w1[q];
                A0 = fma2(sel2[2*q], u0.x, A0); A0 = fma2(sel2[2*q+1], u0.y, A0);
                A1 = fma2(sel2[2*q], u1.x, A1); A1 = fma2(sel2[2*q+1], u1.y, A1);
            }
            float v0 = fmaxf(hadd2(A0) + s[OFF_MB1 + i0],     0.f);
            float v1 = fmaxf(hadd2(A1) + s[OFF_MB1 + i0 + 1], 0.f);
            m1p[k] = pk2(v0, v1);
        }
#pragma unroll
        for (int i = 0; i < 32; i++) {
            const ulonglong2* wr = (const ulonglong2*)&s[OFF_MW2 + i * 64 + c * 16];
            u64t A = 0ull;
#pragma unroll
            for (int q = 0; q < 4; q++) {
                ulonglong2 u = wr[q];
                A = fma2(m1p[2*q], u.x, A); A = fma2(m1p[2*q+1], u.y, A);
            }
            m2[i] += hadd2(A);
        }
    }
    u64t m2p[16];
#pragma unroll
    for (int p = 0; p < 16; p++)
        m2p[p] = pk2(fmaxf(m2[2*p], 0.f), fmaxf(m2[2*p+1], 0.f));

    // Regressor 32->64->1 (FIXED m2p indexing: wr[q] covers floats 4q..4q+3
    // = pairs m2p[2q], m2p[2q+1]; wr[q+4] covers floats 16+4q.. = m2p[8+2q..])
    float acc_out = s[OFF_RB2];
#pragma unroll 4
    for (int i = 0; i < 64; i++) {
        const ulonglong2* wr = (const ulonglong2*)&s[OFF_RW1 + i * 32];
        u64t A = 0ull;
#pragma unroll
        for (int q = 0; q < 4; q++) {
            ulonglong2 u = wr[q];
            A = fma2(m2p[2*q],   u.x, A);
            A = fma2(m2p[2*q+1], u.y, A);
            u = wr[q + 4];
            A = fma2(m2p[8 + 2*q],   u.x, A);
            A = fma2(m2p[8 + 2*q+1], u.y, A);
        }
        float a = fmaxf(hadd2(A) + s[OFF_RB1 + i], 0.f);
        acc_out = fmaf(a, s[OFF_RW2 + i], acc_out);
    }
    out[row] = acc_out;
}

// ---------------------------------------------------------------------------
extern "C" void kernel_launch(void* const* d_in, const int* in_sizes, int n_in,
                              void* d_out, int out_size) {
    const float* x_tab    = (const float*)d_in[0];
    const float* emb_w    = (const float*)d_in[1];
    const float* emb_b    = (const float*)d_in[2];
    const float* grn_w1   = (const float*)d_in[3];
    const float* grn_b1   = (const float*)d_in[4];
    const float* grn_w2   = (const float*)d_in[5];
    const float* grn_b2   = (const float*)d_in[6];
    const float* grn_wg   = (const float*)d_in[7];
    const float* grn_bg   = (const float*)d_in[8];
    const float* grn_ws   = (const float*)d_in[9];
    const float* grn_bs   = (const float*)d_in[10];
    const float* grn_g    = (const float*)d_in[11];
    const float* grn_beta = (const float*)d_in[12];
    const float* wg_w1    = (const float*)d_in[13];
    const float* wg_b1    = (const float*)d_in[14];
    const float* wg_w2    = (const float*)d_in[15];
    const float* wg_b2    = (const float*)d_in[16];
    const float* wg_wgm   = (const float*)d_in[17];
    const float* wg_bg    = (const float*)d_in[18];
    const float* wg_ws    = (const float*)d_in[19];
    const float* wg_bs    = (const float*)d_in[20];
    const float* wg_g     = (const float*)d_in[21];
    const float* wg_beta  = (const float*)d_in[22];
    const float* mlp_w1   = (const float*)d_in[23];
    const float* mlp_b1   = (const float*)d_in[24];
    const float* mlp_w2   = (const float*)d_in[25];
    const float* mlp_b2   = (const float*)d_in[26];
    const float* reg_w1   = (const float*)d_in[27];
    const float* reg_b1   = (const float*)d_in[28];
    const float* reg_w2   = (const float*)d_in[29];
    const float* reg_b2   = (const float*)d_in[30];

    int Bn = in_sizes[0] / FD;
    float* out = (float*)d_out;
    float* wout = (out_size >= Bn * (FD + 1)) ? (out + Bn) : nullptr;

    cudaFuncSetAttribute(sel_mlp_kernel,
                         cudaFuncAttributeMaxDynamicSharedMemorySize,
                         SMEMB_FLOATS * (int)sizeof(float));

    int gridA = (Bn + 255) / 256;   // 128 threads x 2 rows
    var_grn_kernel<<<gridA, 128>>>(x_tab, emb_w, emb_b, grn_w1, grn_b1,
                                   grn_ws, grn_bs, grn_w2, grn_b2, grn_wg,
                                   grn_bg, grn_g, grn_beta, Bn);

    int gridB = (Bn + 127) / 128;   // 128 threads x 1 row
    sel_mlp_kernel<<<gridB, 128, SMEMB_FLOATS * sizeof(float)>>>(
        wg_w1, wg_b1, wg_w2, wg_b2, wg_wgm, wg_bg, wg_ws, wg_bs, wg_g, wg_beta,
        mlp_w1, mlp_b1, mlp_w2, mlp_b2, reg_w1, reg_b1, reg_w2, reg_b2,
        out, wout, Bn);
}